// round 7
// baseline (speedup 1.0000x reference)
#include <cuda_runtime.h>

// Problem constants (shapes are fixed by the dataset).
#define MAXN 50048

// Scratch (module-level device arrays; 16B-aligned for float4 / red.v4 access).
__device__ __align__(16) float g_deg[MAXN];        // degree -> dinv (in place)
__device__ __align__(16) float g_h[MAXN * 96];     // GEMM output H = X @ W
__device__ __align__(16) float g_agg[MAXN * 96];   // scatter accumulator
__device__ __align__(16) float g_bufA[MAXN * 256]; // activation ping
__device__ __align__(16) float g_bufB[MAXN * 256]; // activation pong

// ---------------------------------------------------------------------------
// degree / norm   (edge_index arrives as int32: JAX x64 is disabled upstream)
// ---------------------------------------------------------------------------
__global__ void deg_init_kernel(float* __restrict__ deg, int n) {
    int i = blockIdx.x * blockDim.x + threadIdx.x;
    if (i < n) deg[i] = 1.0f;  // self loop
}

__global__ void deg_acc_kernel(const int* __restrict__ ei, int E,
                               float* __restrict__ deg) {
    int e = blockIdx.x * blockDim.x + threadIdx.x;
    if (e < E) atomicAdd(&deg[ei[E + e]], 1.0f);  // row 1 = dst
}

__global__ void dinv_kernel(float* __restrict__ deg, int n) {
    int i = blockIdx.x * blockDim.x + threadIdx.x;
    if (i < n) deg[i] = rsqrtf(deg[i]);
}

// ---------------------------------------------------------------------------
// GEMM: C[n,K] = A[n,M] @ W[M,K], optional epilogue.
// EPI: 0 = none, 1 = bias+relu, 2 = bias only.
// One thread computes a float4 of output columns for one node.
// ---------------------------------------------------------------------------
template <int M, int K, int EPI>
__global__ void __launch_bounds__(256)
gemm_kernel(const float* __restrict__ A, const float* __restrict__ W,
            const float* __restrict__ bias, float* __restrict__ C, int n) {
    constexpr int KC = K / 4;
    int idx = blockIdx.x * blockDim.x + threadIdx.x;
    if (idx >= n * KC) return;
    int node = idx / KC;
    int c4 = idx - node * KC;

    const float4* A4 = reinterpret_cast<const float4*>(A) + (size_t)node * (M / 4);
    float4 acc = make_float4(0.f, 0.f, 0.f, 0.f);

#pragma unroll 8
    for (int m4 = 0; m4 < M / 4; m4++) {
        float4 a = __ldg(A4 + m4);
        const float* wp = W + (size_t)(m4 * 4) * K + c4 * 4;
        float4 w0 = *reinterpret_cast<const float4*>(wp);
        float4 w1 = *reinterpret_cast<const float4*>(wp + K);
        float4 w2 = *reinterpret_cast<const float4*>(wp + 2 * K);
        float4 w3 = *reinterpret_cast<const float4*>(wp + 3 * K);
        acc.x += a.x * w0.x + a.y * w1.x + a.z * w2.x + a.w * w3.x;
        acc.y += a.x * w0.y + a.y * w1.y + a.z * w2.y + a.w * w3.y;
        acc.z += a.x * w0.z + a.y * w1.z + a.z * w2.z + a.w * w3.z;
        acc.w += a.x * w0.w + a.y * w1.w + a.z * w2.w + a.w * w3.w;
    }

    if (EPI != 0) {
        float4 b = reinterpret_cast<const float4*>(bias)[c4];
        acc.x += b.x; acc.y += b.y; acc.z += b.z; acc.w += b.w;
        if (EPI == 1) {
            acc.x = fmaxf(acc.x, 0.f);
            acc.y = fmaxf(acc.y, 0.f);
            acc.z = fmaxf(acc.z, 0.f);
            acc.w = fmaxf(acc.w, 0.f);
        }
    }
    reinterpret_cast<float4*>(C)[(size_t)node * KC + c4] = acc;
}

// ---------------------------------------------------------------------------
// agg[i,:] = dinv[i]^2 * H[i,:]   (self-loop contribution, also initializes agg)
// ---------------------------------------------------------------------------
__global__ void selfinit_kernel(const float* __restrict__ H,
                                const float* __restrict__ dinv,
                                float* __restrict__ agg, int n) {
    int idx = blockIdx.x * blockDim.x + threadIdx.x;
    if (idx >= n * 24) return;
    int node = idx / 24;
    float d = dinv[node];
    float s = d * d;
    float4 h = reinterpret_cast<const float4*>(H)[idx];
    reinterpret_cast<float4*>(agg)[idx] =
        make_float4(h.x * s, h.y * s, h.z * s, h.w * s);
}

// ---------------------------------------------------------------------------
// Edge scatter: agg[dst,:] += dinv[src]*dinv[dst] * H[src,:]
// Thread per (edge, 4-col chunk); red.global.add.v4.f32 (no return atomic).
// ---------------------------------------------------------------------------
__global__ void __launch_bounds__(256)
scatter_kernel(const int* __restrict__ ei, const float* __restrict__ H,
               const float* __restrict__ dinv, float* __restrict__ agg, int E) {
    int idx = blockIdx.x * blockDim.x + threadIdx.x;
    if (idx >= E * 24) return;
    int e = idx / 24;
    int c = idx - e * 24;
    int s = ei[e];
    int d = ei[E + e];
    float nrm = dinv[s] * dinv[d];
    float4 h = reinterpret_cast<const float4*>(H)[s * 24 + c];
    float* p = agg + (size_t)d * 96 + c * 4;
    asm volatile("red.global.add.v4.f32 [%0], {%1, %2, %3, %4};"
                 :: "l"(p), "f"(h.x * nrm), "f"(h.y * nrm),
                    "f"(h.z * nrm), "f"(h.w * nrm)
                 : "memory");
}

// ---------------------------------------------------------------------------
// Post: out = relu( (agg + b) * g/sqrt(1+eps) + be )
//     = relu( agg*s + (b*s + be) ),  s = g * 1/sqrt(1+1e-5)
// ---------------------------------------------------------------------------
__global__ void post_kernel(const float* __restrict__ agg,
                            const float* __restrict__ b,
                            const float* __restrict__ g,
                            const float* __restrict__ be,
                            float* __restrict__ out, int n) {
    const float INV = 0.99999500003749971f;  // 1/sqrt(1+1e-5)
    int idx = blockIdx.x * blockDim.x + threadIdx.x;
    if (idx >= n * 24) return;
    int c4 = idx % 24;
    float4 gv = reinterpret_cast<const float4*>(g)[c4];
    float4 bv = reinterpret_cast<const float4*>(b)[c4];
    float4 bev = reinterpret_cast<const float4*>(be)[c4];
    float4 a = reinterpret_cast<const float4*>(agg)[idx];
    float sx = gv.x * INV, sy = gv.y * INV, sz = gv.z * INV, sw = gv.w * INV;
    float4 o;
    o.x = fmaxf(a.x * sx + (bv.x * sx + bev.x), 0.f);
    o.y = fmaxf(a.y * sy + (bv.y * sy + bev.y), 0.f);
    o.z = fmaxf(a.z * sz + (bv.z * sz + bev.z), 0.f);
    o.w = fmaxf(a.w * sw + (bv.w * sw + bev.w), 0.f);
    reinterpret_cast<float4*>(out)[idx] = o;
}

// ---------------------------------------------------------------------------
// Launch
// ---------------------------------------------------------------------------
static inline int grid_for(long long threads, int block) {
    return (int)((threads + block - 1) / block);
}

extern "C" void kernel_launch(void* const* d_in, const int* in_sizes, int n_in,
                              void* d_out, int out_size) {
    const float* x  = (const float*)d_in[0];
    const int*   ei = (const int*)d_in[1];   // int32: JAX x64 disabled upstream
    const float* w1 = (const float*)d_in[2];
    const float* b1 = (const float*)d_in[3];
    const float* g1 = (const float*)d_in[4];
    const float* be1 = (const float*)d_in[5];
    const float* w2 = (const float*)d_in[6];
    const float* b2 = (const float*)d_in[7];
    const float* g2 = (const float*)d_in[8];
    const float* be2 = (const float*)d_in[9];
    const float* w3 = (const float*)d_in[10];
    const float* b3 = (const float*)d_in[11];
    const float* g3 = (const float*)d_in[12];
    const float* be3 = (const float*)d_in[13];
    const float* lw1 = (const float*)d_in[14];
    const float* lb1 = (const float*)d_in[15];
    const float* lw2 = (const float*)d_in[16];
    const float* lb2 = (const float*)d_in[17];
    const float* lw3 = (const float*)d_in[18];
    const float* lb3 = (const float*)d_in[19];
    const float* lw4 = (const float*)d_in[20];
    const float* lb4 = (const float*)d_in[21];
    float* out = (float*)d_out;

    const int N = in_sizes[0] / 64;
    const int E = in_sizes[1] / 2;

    float *deg, *h, *agg, *bufA, *bufB;
    cudaGetSymbolAddress((void**)&deg,  g_deg);
    cudaGetSymbolAddress((void**)&h,    g_h);
    cudaGetSymbolAddress((void**)&agg,  g_agg);
    cudaGetSymbolAddress((void**)&bufA, g_bufA);
    cudaGetSymbolAddress((void**)&bufB, g_bufB);

    const int BLK = 256;

    // --- norms ---
    deg_init_kernel<<<grid_for(N, BLK), BLK>>>(deg, N);
    deg_acc_kernel<<<grid_for(E, BLK), BLK>>>(ei, E, deg);
    dinv_kernel<<<grid_for(N, BLK), BLK>>>(deg, N);  // deg now holds dinv

    const long long nodeElems = (long long)N * 24;     // N*96/4
    const long long edgeElems = (long long)E * 24;

    // --- GCN layer 1 (in: x [N,64]) ---
    gemm_kernel<64, 96, 0><<<grid_for(nodeElems, BLK), BLK>>>(x, w1, nullptr, h, N);
    selfinit_kernel<<<grid_for(nodeElems, BLK), BLK>>>(h, deg, agg, N);
    scatter_kernel<<<grid_for(edgeElems, BLK), BLK>>>(ei, h, deg, agg, E);
    post_kernel<<<grid_for(nodeElems, BLK), BLK>>>(agg, b1, g1, be1, bufA, N);

    // --- GCN layer 2 ---
    gemm_kernel<96, 96, 0><<<grid_for(nodeElems, BLK), BLK>>>(bufA, w2, nullptr, h, N);
    selfinit_kernel<<<grid_for(nodeElems, BLK), BLK>>>(h, deg, agg, N);
    scatter_kernel<<<grid_for(edgeElems, BLK), BLK>>>(ei, h, deg, agg, E);
    post_kernel<<<grid_for(nodeElems, BLK), BLK>>>(agg, b2, g2, be2, bufB, N);

    // --- GCN layer 3 ---
    gemm_kernel<96, 96, 0><<<grid_for(nodeElems, BLK), BLK>>>(bufB, w3, nullptr, h, N);
    selfinit_kernel<<<grid_for(nodeElems, BLK), BLK>>>(h, deg, agg, N);
    scatter_kernel<<<grid_for(edgeElems, BLK), BLK>>>(ei, h, deg, agg, E);
    post_kernel<<<grid_for(nodeElems, BLK), BLK>>>(agg, b3, g3, be3, bufA, N);

    // --- MLP head ---
    gemm_kernel<96, 256, 1><<<grid_for((long long)N * 64, BLK), BLK>>>(bufA, lw1, lb1, bufB, N);
    gemm_kernel<256, 128, 1><<<grid_for((long long)N * 32, BLK), BLK>>>(bufB, lw2, lb2, bufA, N);
    gemm_kernel<128, 64, 1><<<grid_for((long long)N * 16, BLK), BLK>>>(bufA, lw3, lb3, bufB, N);
    gemm_kernel<64, 8, 2><<<grid_for((long long)N * 2, BLK), BLK>>>(bufB, lw4, lb4, out, N);
}

// round 8
// speedup vs baseline: 1.7385x; 1.7385x over previous
#include <cuda_runtime.h>

// Problem constants (dataset-fixed shapes; margins included).
#define MAXN 50048
#define MAXE 1000000

// Scratch (module-level device arrays; 16B-aligned for vector access).
__device__ __align__(16) int   g_cnt[MAXN];          // in-degree counts
__device__ __align__(16) int   g_off[MAXN];          // CSR offsets (exclusive scan)
__device__ __align__(16) int   g_cursor[MAXN];       // fill cursors
__device__ __align__(16) int   g_partial[256];       // scan partials
__device__ __align__(16) int   g_csr_src[MAXE];      // CSR adjacency (src per dst)
__device__ __align__(16) float g_dinv[MAXN];         // 1/sqrt(deg)
__device__ __align__(16) float g_h[MAXN * 96];       // GEMM output H = X @ W
__device__ __align__(16) float g_bufA[MAXN * 256];   // activation ping
__device__ __align__(16) float g_bufB[MAXN * 256];   // activation pong

// ---------------------------------------------------------------------------
// CSR build: count -> scan -> fill.  edge_index is int32 (JAX x64 disabled).
// ---------------------------------------------------------------------------
__global__ void zero_cnt_kernel(int* __restrict__ cnt, int n) {
    int i = blockIdx.x * blockDim.x + threadIdx.x;
    if (i < n) cnt[i] = 0;
}

__global__ void count_kernel(const int* __restrict__ ei, int E,
                             int* __restrict__ cnt) {
    int e = blockIdx.x * blockDim.x + threadIdx.x;
    if (e < E) atomicAdd(&cnt[ei[E + e]], 1);  // row 1 = dst
}

__global__ void dinv_kernel(const int* __restrict__ cnt, float* __restrict__ dinv,
                            int n) {
    int i = blockIdx.x * blockDim.x + threadIdx.x;
    if (i < n) dinv[i] = rsqrtf(1.0f + (float)cnt[i]);  // +1 self loop
}

// Block-level exclusive scan, 1024 elems/block (Hillis-Steele).
__global__ void scan1_kernel(const int* __restrict__ cnt, int n,
                             int* __restrict__ off, int* __restrict__ partial) {
    __shared__ int sm[1024];
    int t = threadIdx.x;
    int i = blockIdx.x * 1024 + t;
    int v = (i < n) ? cnt[i] : 0;
    sm[t] = v;
    __syncthreads();
#pragma unroll
    for (int ofs = 1; ofs < 1024; ofs <<= 1) {
        int add = (t >= ofs) ? sm[t - ofs] : 0;
        __syncthreads();
        sm[t] += add;
        __syncthreads();
    }
    if (i < n) off[i] = sm[t] - v;  // exclusive
    if (t == 1023) partial[blockIdx.x] = sm[t];
}

__global__ void scan2_kernel(int* __restrict__ partial, int nb) {
    __shared__ int sm[256];
    int t = threadIdx.x;
    int v = (t < nb) ? partial[t] : 0;
    sm[t] = v;
    __syncthreads();
#pragma unroll
    for (int ofs = 1; ofs < 256; ofs <<= 1) {
        int add = (t >= ofs) ? sm[t - ofs] : 0;
        __syncthreads();
        sm[t] += add;
        __syncthreads();
    }
    if (t < nb) partial[t] = sm[t] - v;  // exclusive
}

__global__ void scan3_kernel(int* __restrict__ off, const int* __restrict__ partial,
                             int* __restrict__ cursor, int n) {
    int i = blockIdx.x * blockDim.x + threadIdx.x;
    if (i < n) {
        int o = off[i] + partial[i >> 10];
        off[i] = o;
        cursor[i] = o;
    }
}

__global__ void fill_kernel(const int* __restrict__ ei, int E,
                            int* __restrict__ cursor, int* __restrict__ csr_src) {
    int e = blockIdx.x * blockDim.x + threadIdx.x;
    if (e < E) {
        int s = ei[e];
        int d = ei[E + e];
        int pos = atomicAdd(&cursor[d], 1);
        csr_src[pos] = s;
    }
}

// ---------------------------------------------------------------------------
// GEMM: C[n,K] = A[n,M] @ W[M,K]. Register-blocked 4 nodes x 4 cols per
// thread, packed fma.rn.f32x2 (2 FP32 FMA per fma-pipe issue).
// EPI: 0 = none, 1 = bias+relu, 2 = bias only.
// ---------------------------------------------------------------------------
template <int M, int K, int EPI>
__global__ void __launch_bounds__(256)
gemm4_kernel(const float* __restrict__ A, const float* __restrict__ W,
             const float* __restrict__ bias, float* __restrict__ C, int n) {
    constexpr int KC = K / 4;
    constexpr int MS = M / 4;
    int idx = blockIdx.x * blockDim.x + threadIdx.x;
    int ng = idx / KC;
    int c4 = idx - ng * KC;
    int n0 = ng * 4;
    if (n0 >= n) return;
    // Clamp for safety on a ragged tail (n is a multiple of 4 in this dataset).
    int i1 = (n0 + 1 < n) ? 1 : 0;
    int i2 = (n0 + 2 < n) ? 2 : 0;
    int i3 = (n0 + 3 < n) ? 3 : 0;

    const float4* A4 = reinterpret_cast<const float4*>(A);
    unsigned long long acc[4][2] = {};  // 4 nodes x (2 packed f32x2 = 4 cols)

#pragma unroll
    for (int m4 = 0; m4 < MS; m4++) {
        float4 a0 = __ldg(A4 + (size_t)(n0)*MS + m4);
        float4 a1 = __ldg(A4 + (size_t)(n0 + i1) * MS + m4);
        float4 a2 = __ldg(A4 + (size_t)(n0 + i2) * MS + m4);
        float4 a3 = __ldg(A4 + (size_t)(n0 + i3) * MS + m4);
        const ulonglong2* wp =
            reinterpret_cast<const ulonglong2*>(W + (size_t)(m4 * 4) * K) + c4;
#pragma unroll
        for (int r = 0; r < 4; r++) {
            ulonglong2 w = wp[r * KC];
            float av0 = r == 0 ? a0.x : r == 1 ? a0.y : r == 2 ? a0.z : a0.w;
            float av1 = r == 0 ? a1.x : r == 1 ? a1.y : r == 2 ? a1.z : a1.w;
            float av2 = r == 0 ? a2.x : r == 1 ? a2.y : r == 2 ? a2.z : a2.w;
            float av3 = r == 0 ? a3.x : r == 1 ? a3.y : r == 2 ? a3.z : a3.w;
            unsigned long long p0, p1, p2, p3;
            asm("mov.b64 %0, {%1,%1};" : "=l"(p0) : "f"(av0));
            asm("mov.b64 %0, {%1,%1};" : "=l"(p1) : "f"(av1));
            asm("mov.b64 %0, {%1,%1};" : "=l"(p2) : "f"(av2));
            asm("mov.b64 %0, {%1,%1};" : "=l"(p3) : "f"(av3));
            asm("fma.rn.f32x2 %0, %1, %2, %0;" : "+l"(acc[0][0]) : "l"(p0), "l"(w.x));
            asm("fma.rn.f32x2 %0, %1, %2, %0;" : "+l"(acc[0][1]) : "l"(p0), "l"(w.y));
            asm("fma.rn.f32x2 %0, %1, %2, %0;" : "+l"(acc[1][0]) : "l"(p1), "l"(w.x));
            asm("fma.rn.f32x2 %0, %1, %2, %0;" : "+l"(acc[1][1]) : "l"(p1), "l"(w.y));
            asm("fma.rn.f32x2 %0, %1, %2, %0;" : "+l"(acc[2][0]) : "l"(p2), "l"(w.x));
            asm("fma.rn.f32x2 %0, %1, %2, %0;" : "+l"(acc[2][1]) : "l"(p2), "l"(w.y));
            asm("fma.rn.f32x2 %0, %1, %2, %0;" : "+l"(acc[3][0]) : "l"(p3), "l"(w.x));
            asm("fma.rn.f32x2 %0, %1, %2, %0;" : "+l"(acc[3][1]) : "l"(p3), "l"(w.y));
        }
    }

    float4 bv;
    if (EPI != 0) bv = reinterpret_cast<const float4*>(bias)[c4];

#pragma unroll
    for (int i = 0; i < 4; i++) {
        int node = n0 + i;
        if (node >= n) break;
        float2 lo = *reinterpret_cast<float2*>(&acc[i][0]);
        float2 hi = *reinterpret_cast<float2*>(&acc[i][1]);
        float4 o = make_float4(lo.x, lo.y, hi.x, hi.y);
        if (EPI != 0) {
            o.x += bv.x; o.y += bv.y; o.z += bv.z; o.w += bv.w;
            if (EPI == 1) {
                o.x = fmaxf(o.x, 0.f);
                o.y = fmaxf(o.y, 0.f);
                o.z = fmaxf(o.z, 0.f);
                o.w = fmaxf(o.w, 0.f);
            }
        }
        reinterpret_cast<float4*>(C)[(size_t)node * KC + c4] = o;
    }
}

// ---------------------------------------------------------------------------
// CSR gather, fused self-loop + bias + BN(eval) + ReLU epilogue.
// One block of 96 threads per dst node; thread c owns channel c.
// out[v,c] = relu( (sum_u norm*H[u,c] + dinv[v]^2*H[v,c] + b[c]) * s[c] + be[c] )
// with s = g / sqrt(1+eps).
// ---------------------------------------------------------------------------
__global__ void __launch_bounds__(96)
gather_kernel(const int* __restrict__ off, const int* __restrict__ cnt,
              const int* __restrict__ csr_src, const float* __restrict__ dinv,
              const float* __restrict__ H, const float* __restrict__ b,
              const float* __restrict__ g, const float* __restrict__ be,
              float* __restrict__ out, int n) {
    __shared__ int   s_src[96];
    __shared__ float s_w[96];
    int node = blockIdx.x;
    int c = threadIdx.x;
    float dd = dinv[node];
    float acc = dd * dd * H[node * 96 + c];  // self loop
    int start = off[node];
    int deg = cnt[node];
    for (int base = 0; base < deg; base += 96) {
        int m = min(96, deg - base);
        if (c < m) {
            int s = csr_src[start + base + c];
            s_src[c] = s;
            s_w[c] = dinv[s] * dd;
        }
        __syncthreads();
#pragma unroll 4
        for (int j = 0; j < m; j++)
            acc = fmaf(s_w[j], __ldg(H + (size_t)s_src[j] * 96 + c), acc);
        __syncthreads();
    }
    const float INV = 0.99999500003749971f;  // 1/sqrt(1+1e-5)
    float s1 = g[c] * INV;
    out[node * 96 + c] = fmaxf(fmaf(acc + b[c], s1, be[c]), 0.f);
}

// ---------------------------------------------------------------------------
// Launch
// ---------------------------------------------------------------------------
static inline int grid_for(long long threads, int block) {
    return (int)((threads + block - 1) / block);
}

extern "C" void kernel_launch(void* const* d_in, const int* in_sizes, int n_in,
                              void* d_out, int out_size) {
    const float* x  = (const float*)d_in[0];
    const int*   ei = (const int*)d_in[1];   // int32
    const float* w1 = (const float*)d_in[2];
    const float* b1 = (const float*)d_in[3];
    const float* g1 = (const float*)d_in[4];
    const float* be1 = (const float*)d_in[5];
    const float* w2 = (const float*)d_in[6];
    const float* b2 = (const float*)d_in[7];
    const float* g2 = (const float*)d_in[8];
    const float* be2 = (const float*)d_in[9];
    const float* w3 = (const float*)d_in[10];
    const float* b3 = (const float*)d_in[11];
    const float* g3 = (const float*)d_in[12];
    const float* be3 = (const float*)d_in[13];
    const float* lw1 = (const float*)d_in[14];
    const float* lb1 = (const float*)d_in[15];
    const float* lw2 = (const float*)d_in[16];
    const float* lb2 = (const float*)d_in[17];
    const float* lw3 = (const float*)d_in[18];
    const float* lb3 = (const float*)d_in[19];
    const float* lw4 = (const float*)d_in[20];
    const float* lb4 = (const float*)d_in[21];
    float* out = (float*)d_out;

    const int N = in_sizes[0] / 64;
    const int E = in_sizes[1] / 2;

    int *cnt, *off, *cursor, *partial, *csr_src;
    float *dinv, *h, *bufA, *bufB;
    cudaGetSymbolAddress((void**)&cnt,     g_cnt);
    cudaGetSymbolAddress((void**)&off,     g_off);
    cudaGetSymbolAddress((void**)&cursor,  g_cursor);
    cudaGetSymbolAddress((void**)&partial, g_partial);
    cudaGetSymbolAddress((void**)&csr_src, g_csr_src);
    cudaGetSymbolAddress((void**)&dinv,    g_dinv);
    cudaGetSymbolAddress((void**)&h,       g_h);
    cudaGetSymbolAddress((void**)&bufA,    g_bufA);
    cudaGetSymbolAddress((void**)&bufB,    g_bufB);

    const int BLK = 256;
    const int nb = (N + 1023) / 1024;  // scan blocks (<=256)

    // --- CSR build + norms ---
    zero_cnt_kernel<<<grid_for(N, BLK), BLK>>>(cnt, N);
    count_kernel<<<grid_for(E, BLK), BLK>>>(ei, E, cnt);
    dinv_kernel<<<grid_for(N, BLK), BLK>>>(cnt, dinv, N);
    scan1_kernel<<<nb, 1024>>>(cnt, N, off, partial);
    scan2_kernel<<<1, 256>>>(partial, nb);
    scan3_kernel<<<grid_for(N, BLK), BLK>>>(off, partial, cursor, N);
    fill_kernel<<<grid_for(E, BLK), BLK>>>(ei, E, cursor, csr_src);

    // --- GCN layer 1 (in: x [N,64]) ---
    gemm4_kernel<64, 96, 0><<<grid_for((long long)((N + 3) / 4) * 24, BLK), BLK>>>(x, w1, nullptr, h, N);
    gather_kernel<<<N, 96>>>(off, cnt, csr_src, dinv, h, b1, g1, be1, bufA, N);

    // --- GCN layer 2 ---
    gemm4_kernel<96, 96, 0><<<grid_for((long long)((N + 3) / 4) * 24, BLK), BLK>>>(bufA, w2, nullptr, h, N);
    gather_kernel<<<N, 96>>>(off, cnt, csr_src, dinv, h, b2, g2, be2, bufB, N);

    // --- GCN layer 3 ---
    gemm4_kernel<96, 96, 0><<<grid_for((long long)((N + 3) / 4) * 24, BLK), BLK>>>(bufB, w3, nullptr, h, N);
    gather_kernel<<<N, 96>>>(off, cnt, csr_src, dinv, h, b3, g3, be3, bufA, N);

    // --- MLP head ---
    gemm4_kernel<96, 256, 1><<<grid_for((long long)((N + 3) / 4) * 64, BLK), BLK>>>(bufA, lw1, lb1, bufB, N);
    gemm4_kernel<256, 128, 1><<<grid_for((long long)((N + 3) / 4) * 32, BLK), BLK>>>(bufB, lw2, lb2, bufA, N);
    gemm4_kernel<128, 64, 1><<<grid_for((long long)((N + 3) / 4) * 16, BLK), BLK>>>(bufA, lw3, lb3, bufB, N);
    gemm4_kernel<64, 8, 2><<<grid_for((long long)((N + 3) / 4) * 2, BLK), BLK>>>(bufB, lw4, lb4, out, N);
}

// round 9
// speedup vs baseline: 1.8177x; 1.0456x over previous
#include <cuda_runtime.h>

// Problem constants (dataset-fixed shapes; margins included).
#define MAXN 50048
#define MAXE 1000000

// Scratch (module-level device arrays; 16B-aligned for vector access).
__device__ __align__(16) int   g_cnt[MAXN];          // in-degree counts
__device__ __align__(16) int   g_off[MAXN];          // CSR offsets (exclusive scan)
__device__ __align__(16) int   g_cursor[MAXN];       // fill cursors
__device__ __align__(16) int   g_partial[256];       // scan partials
__device__ __align__(16) int   g_csr_src[MAXE];      // CSR adjacency (src per dst)
__device__ __align__(16) float g_dinv[MAXN];         // 1/sqrt(deg)
__device__ __align__(16) float g_agg[MAXN * 96];     // aggregated features
__device__ __align__(16) float g_bufA[MAXN * 256];   // activation ping
__device__ __align__(16) float g_bufB[MAXN * 256];   // activation pong

// ---------------------------------------------------------------------------
// CSR build: count -> scan -> fill.  edge_index is int32 (JAX x64 disabled).
// ---------------------------------------------------------------------------
__global__ void zero_cnt_kernel(int* __restrict__ cnt, int n) {
    int i = blockIdx.x * blockDim.x + threadIdx.x;
    if (i < n) cnt[i] = 0;
}

__global__ void count_kernel(const int* __restrict__ ei, int E,
                             int* __restrict__ cnt) {
    int e = blockIdx.x * blockDim.x + threadIdx.x;
    if (e < E) atomicAdd(&cnt[ei[E + e]], 1);  // row 1 = dst
}

// Block-level exclusive scan, 1024 elems/block (Hillis-Steele).
__global__ void scan1_kernel(const int* __restrict__ cnt, int n,
                             int* __restrict__ off, int* __restrict__ partial) {
    __shared__ int sm[1024];
    int t = threadIdx.x;
    int i = blockIdx.x * 1024 + t;
    int v = (i < n) ? cnt[i] : 0;
    sm[t] = v;
    __syncthreads();
#pragma unroll
    for (int ofs = 1; ofs < 1024; ofs <<= 1) {
        int add = (t >= ofs) ? sm[t - ofs] : 0;
        __syncthreads();
        sm[t] += add;
        __syncthreads();
    }
    if (i < n) off[i] = sm[t] - v;  // exclusive
    if (t == 1023) partial[blockIdx.x] = sm[t];
}

__global__ void scan2_kernel(int* __restrict__ partial, int nb) {
    __shared__ int sm[256];
    int t = threadIdx.x;
    int v = (t < nb) ? partial[t] : 0;
    sm[t] = v;
    __syncthreads();
#pragma unroll
    for (int ofs = 1; ofs < 256; ofs <<= 1) {
        int add = (t >= ofs) ? sm[t - ofs] : 0;
        __syncthreads();
        sm[t] += add;
        __syncthreads();
    }
    if (t < nb) partial[t] = sm[t] - v;  // exclusive
}

// Finalize offsets + cursors + dinv in one pass.
__global__ void scan3_kernel(int* __restrict__ off, const int* __restrict__ partial,
                             int* __restrict__ cursor, const int* __restrict__ cnt,
                             float* __restrict__ dinv, int n) {
    int i = blockIdx.x * blockDim.x + threadIdx.x;
    if (i < n) {
        int o = off[i] + partial[i >> 10];
        off[i] = o;
        cursor[i] = o;
        dinv[i] = rsqrtf(1.0f + (float)cnt[i]);  // +1 self loop
    }
}

__global__ void fill_kernel(const int* __restrict__ ei, int E,
                            int* __restrict__ cursor, int* __restrict__ csr_src) {
    int e = blockIdx.x * blockDim.x + threadIdx.x;
    if (e < E) {
        int s = ei[e];
        int d = ei[E + e];
        int pos = atomicAdd(&cursor[d], 1);
        csr_src[pos] = s;
    }
}

// ---------------------------------------------------------------------------
// Aggregation (A(X) with GCN norm + self loop), thread-per-(node, 4 channels).
// agg[v,c] = dinv[v]^2 * X[v,c] + sum_u dinv[u]*dinv[v] * X[u,c]
// No smem, no barriers; inner loop unrolled x4 for MLP.
// ---------------------------------------------------------------------------
template <int C4>  // channels/4
__global__ void __launch_bounds__(256)
agg_kernel(const int* __restrict__ off, const int* __restrict__ cnt,
           const int* __restrict__ csr_src, const float* __restrict__ dinv,
           const float* __restrict__ X, float* __restrict__ out, int n) {
    int idx = blockIdx.x * blockDim.x + threadIdx.x;
    int node = idx / C4;
    int c4 = idx - node * C4;
    if (node >= n) return;

    const float4* X4 = reinterpret_cast<const float4*>(X);
    float dd = dinv[node];
    float4 x0 = __ldg(X4 + (size_t)node * C4 + c4);
    float s2 = dd * dd;
    float4 acc = make_float4(x0.x * s2, x0.y * s2, x0.z * s2, x0.w * s2);

    int start = off[node];
    int deg = cnt[node];
    const int* cp = csr_src + start;

    int j = 0;
    for (; j + 4 <= deg; j += 4) {
        int s0 = __ldg(cp + j);
        int s1 = __ldg(cp + j + 1);
        int s2i = __ldg(cp + j + 2);
        int s3 = __ldg(cp + j + 3);
        float w0 = __ldg(dinv + s0) * dd;
        float w1 = __ldg(dinv + s1) * dd;
        float w2 = __ldg(dinv + s2i) * dd;
        float w3 = __ldg(dinv + s3) * dd;
        float4 h0 = __ldg(X4 + (size_t)s0 * C4 + c4);
        float4 h1 = __ldg(X4 + (size_t)s1 * C4 + c4);
        float4 h2 = __ldg(X4 + (size_t)s2i * C4 + c4);
        float4 h3 = __ldg(X4 + (size_t)s3 * C4 + c4);
        acc.x = fmaf(w0, h0.x, acc.x); acc.y = fmaf(w0, h0.y, acc.y);
        acc.z = fmaf(w0, h0.z, acc.z); acc.w = fmaf(w0, h0.w, acc.w);
        acc.x = fmaf(w1, h1.x, acc.x); acc.y = fmaf(w1, h1.y, acc.y);
        acc.z = fmaf(w1, h1.z, acc.z); acc.w = fmaf(w1, h1.w, acc.w);
        acc.x = fmaf(w2, h2.x, acc.x); acc.y = fmaf(w2, h2.y, acc.y);
        acc.z = fmaf(w2, h2.z, acc.z); acc.w = fmaf(w2, h2.w, acc.w);
        acc.x = fmaf(w3, h3.x, acc.x); acc.y = fmaf(w3, h3.y, acc.y);
        acc.z = fmaf(w3, h3.z, acc.z); acc.w = fmaf(w3, h3.w, acc.w);
    }
    for (; j < deg; j++) {
        int s = __ldg(cp + j);
        float w = __ldg(dinv + s) * dd;
        float4 hv = __ldg(X4 + (size_t)s * C4 + c4);
        acc.x = fmaf(w, hv.x, acc.x); acc.y = fmaf(w, hv.y, acc.y);
        acc.z = fmaf(w, hv.z, acc.z); acc.w = fmaf(w, hv.w, acc.w);
    }
    reinterpret_cast<float4*>(out)[(size_t)node * C4 + c4] = acc;
}

// ---------------------------------------------------------------------------
// GEMM: C[n,K] = A[n,M] @ W[M,K]. Register-blocked 4 nodes x 4 cols per
// thread, packed fma.rn.f32x2 (2 FP32 FMA per fma-pipe issue).
// EPI: 0 none, 1 bias+relu, 2 bias, 3 bias+BN(eval)+relu.
// ---------------------------------------------------------------------------
template <int M, int K, int EPI>
__global__ void __launch_bounds__(256)
gemm4_kernel(const float* __restrict__ A, const float* __restrict__ W,
             const float* __restrict__ bias, const float* __restrict__ gamma,
             const float* __restrict__ beta, float* __restrict__ C, int n) {
    constexpr int KC = K / 4;
    constexpr int MS = M / 4;
    int idx = blockIdx.x * blockDim.x + threadIdx.x;
    int ng = idx / KC;
    int c4 = idx - ng * KC;
    int n0 = ng * 4;
    if (n0 >= n) return;
    int i1 = (n0 + 1 < n) ? 1 : 0;
    int i2 = (n0 + 2 < n) ? 2 : 0;
    int i3 = (n0 + 3 < n) ? 3 : 0;

    const float4* A4 = reinterpret_cast<const float4*>(A);
    unsigned long long acc[4][2] = {};  // 4 nodes x (2 packed f32x2 = 4 cols)

#pragma unroll
    for (int m4 = 0; m4 < MS; m4++) {
        float4 a0 = __ldg(A4 + (size_t)(n0)*MS + m4);
        float4 a1 = __ldg(A4 + (size_t)(n0 + i1) * MS + m4);
        float4 a2 = __ldg(A4 + (size_t)(n0 + i2) * MS + m4);
        float4 a3 = __ldg(A4 + (size_t)(n0 + i3) * MS + m4);
        const ulonglong2* wp =
            reinterpret_cast<const ulonglong2*>(W + (size_t)(m4 * 4) * K) + c4;
#pragma unroll
        for (int r = 0; r < 4; r++) {
            ulonglong2 w = wp[r * KC];
            float av0 = r == 0 ? a0.x : r == 1 ? a0.y : r == 2 ? a0.z : a0.w;
            float av1 = r == 0 ? a1.x : r == 1 ? a1.y : r == 2 ? a1.z : a1.w;
            float av2 = r == 0 ? a2.x : r == 1 ? a2.y : r == 2 ? a2.z : a2.w;
            float av3 = r == 0 ? a3.x : r == 1 ? a3.y : r == 2 ? a3.z : a3.w;
            unsigned long long p0, p1, p2, p3;
            asm("mov.b64 %0, {%1,%1};" : "=l"(p0) : "f"(av0));
            asm("mov.b64 %0, {%1,%1};" : "=l"(p1) : "f"(av1));
            asm("mov.b64 %0, {%1,%1};" : "=l"(p2) : "f"(av2));
            asm("mov.b64 %0, {%1,%1};" : "=l"(p3) : "f"(av3));
            asm("fma.rn.f32x2 %0, %1, %2, %0;" : "+l"(acc[0][0]) : "l"(p0), "l"(w.x));
            asm("fma.rn.f32x2 %0, %1, %2, %0;" : "+l"(acc[0][1]) : "l"(p0), "l"(w.y));
            asm("fma.rn.f32x2 %0, %1, %2, %0;" : "+l"(acc[1][0]) : "l"(p1), "l"(w.x));
            asm("fma.rn.f32x2 %0, %1, %2, %0;" : "+l"(acc[1][1]) : "l"(p1), "l"(w.y));
            asm("fma.rn.f32x2 %0, %1, %2, %0;" : "+l"(acc[2][0]) : "l"(p2), "l"(w.x));
            asm("fma.rn.f32x2 %0, %1, %2, %0;" : "+l"(acc[2][1]) : "l"(p2), "l"(w.y));
            asm("fma.rn.f32x2 %0, %1, %2, %0;" : "+l"(acc[3][0]) : "l"(p3), "l"(w.x));
            asm("fma.rn.f32x2 %0, %1, %2, %0;" : "+l"(acc[3][1]) : "l"(p3), "l"(w.y));
        }
    }

    float4 bv = make_float4(0.f, 0.f, 0.f, 0.f);
    float4 gs = make_float4(0.f, 0.f, 0.f, 0.f);
    float4 bev = make_float4(0.f, 0.f, 0.f, 0.f);
    if (EPI != 0) bv = reinterpret_cast<const float4*>(bias)[c4];
    if (EPI == 3) {
        const float INV = 0.99999500003749971f;  // 1/sqrt(1+1e-5)
        float4 gv = reinterpret_cast<const float4*>(gamma)[c4];
        gs = make_float4(gv.x * INV, gv.y * INV, gv.z * INV, gv.w * INV);
        bev = reinterpret_cast<const float4*>(beta)[c4];
    }

#pragma unroll
    for (int i = 0; i < 4; i++) {
        int node = n0 + i;
        if (node >= n) break;
        float2 lo = *reinterpret_cast<float2*>(&acc[i][0]);
        float2 hi = *reinterpret_cast<float2*>(&acc[i][1]);
        float4 o = make_float4(lo.x, lo.y, hi.x, hi.y);
        if (EPI == 1 || EPI == 2) {
            o.x += bv.x; o.y += bv.y; o.z += bv.z; o.w += bv.w;
            if (EPI == 1) {
                o.x = fmaxf(o.x, 0.f); o.y = fmaxf(o.y, 0.f);
                o.z = fmaxf(o.z, 0.f); o.w = fmaxf(o.w, 0.f);
            }
        } else if (EPI == 3) {
            o.x = fmaxf(fmaf(o.x + bv.x, gs.x, bev.x), 0.f);
            o.y = fmaxf(fmaf(o.y + bv.y, gs.y, bev.y), 0.f);
            o.z = fmaxf(fmaf(o.z + bv.z, gs.z, bev.z), 0.f);
            o.w = fmaxf(fmaf(o.w + bv.w, gs.w, bev.w), 0.f);
        }
        reinterpret_cast<float4*>(C)[(size_t)node * KC + c4] = o;
    }
}

// ---------------------------------------------------------------------------
// Launch
// ---------------------------------------------------------------------------
static inline int grid_for(long long threads, int block) {
    return (int)((threads + block - 1) / block);
}

extern "C" void kernel_launch(void* const* d_in, const int* in_sizes, int n_in,
                              void* d_out, int out_size) {
    const float* x  = (const float*)d_in[0];
    const int*   ei = (const int*)d_in[1];   // int32
    const float* w1 = (const float*)d_in[2];
    const float* b1 = (const float*)d_in[3];
    const float* g1 = (const float*)d_in[4];
    const float* be1 = (const float*)d_in[5];
    const float* w2 = (const float*)d_in[6];
    const float* b2 = (const float*)d_in[7];
    const float* g2 = (const float*)d_in[8];
    const float* be2 = (const float*)d_in[9];
    const float* w3 = (const float*)d_in[10];
    const float* b3 = (const float*)d_in[11];
    const float* g3 = (const float*)d_in[12];
    const float* be3 = (const float*)d_in[13];
    const float* lw1 = (const float*)d_in[14];
    const float* lb1 = (const float*)d_in[15];
    const float* lw2 = (const float*)d_in[16];
    const float* lb2 = (const float*)d_in[17];
    const float* lw3 = (const float*)d_in[18];
    const float* lb3 = (const float*)d_in[19];
    const float* lw4 = (const float*)d_in[20];
    const float* lb4 = (const float*)d_in[21];
    float* out = (float*)d_out;

    const int N = in_sizes[0] / 64;
    const int E = in_sizes[1] / 2;

    int *cnt, *off, *cursor, *partial, *csr_src;
    float *dinv, *agg, *bufA, *bufB;
    cudaGetSymbolAddress((void**)&cnt,     g_cnt);
    cudaGetSymbolAddress((void**)&off,     g_off);
    cudaGetSymbolAddress((void**)&cursor,  g_cursor);
    cudaGetSymbolAddress((void**)&partial, g_partial);
    cudaGetSymbolAddress((void**)&csr_src, g_csr_src);
    cudaGetSymbolAddress((void**)&dinv,    g_dinv);
    cudaGetSymbolAddress((void**)&agg,     g_agg);
    cudaGetSymbolAddress((void**)&bufA,    g_bufA);
    cudaGetSymbolAddress((void**)&bufB,    g_bufB);

    const int BLK = 256;
    const int nb = (N + 1023) / 1024;  // scan blocks (<=256)

    // --- CSR build + norms ---
    zero_cnt_kernel<<<grid_for(N, BLK), BLK>>>(cnt, N);
    count_kernel<<<grid_for(E, BLK), BLK>>>(ei, E, cnt);
    scan1_kernel<<<nb, 1024>>>(cnt, N, off, partial);
    scan2_kernel<<<1, 256>>>(partial, nb);
    scan3_kernel<<<grid_for(N, BLK), BLK>>>(off, partial, cursor, cnt, dinv, N);
    fill_kernel<<<grid_for(E, BLK), BLK>>>(ei, E, cursor, csr_src);

    const long long ngrp = (N + 3) / 4;

    // --- GCN layer 1: aggregate x (64ch) first, then GEMM 64->96 + BN+ReLU ---
    agg_kernel<16><<<grid_for((long long)N * 16, BLK), BLK>>>(off, cnt, csr_src, dinv, x, agg, N);
    gemm4_kernel<64, 96, 3><<<grid_for(ngrp * 24, BLK), BLK>>>(agg, w1, b1, g1, be1, bufA, N);

    // --- GCN layer 2 ---
    agg_kernel<24><<<grid_for((long long)N * 24, BLK), BLK>>>(off, cnt, csr_src, dinv, bufA, agg, N);
    gemm4_kernel<96, 96, 3><<<grid_for(ngrp * 24, BLK), BLK>>>(agg, w2, b2, g2, be2, bufB, N);

    // --- GCN layer 3 ---
    agg_kernel<24><<<grid_for((long long)N * 24, BLK), BLK>>>(off, cnt, csr_src, dinv, bufB, agg, N);
    gemm4_kernel<96, 96, 3><<<grid_for(ngrp * 24, BLK), BLK>>>(agg, w3, b3, g3, be3, bufA, N);

    // --- MLP head ---
    gemm4_kernel<96, 256, 1><<<grid_for(ngrp * 64, BLK), BLK>>>(bufA, lw1, lb1, nullptr, nullptr, bufB, N);
    gemm4_kernel<256, 128, 1><<<grid_for(ngrp * 32, BLK), BLK>>>(bufB, lw2, lb2, nullptr, nullptr, bufA, N);
    gemm4_kernel<128, 64, 1><<<grid_for(ngrp * 16, BLK), BLK>>>(bufA, lw3, lb3, nullptr, nullptr, bufB, N);
    gemm4_kernel<64, 8, 2><<<grid_for(ngrp * 2, BLK), BLK>>>(bufB, lw4, lb4, nullptr, nullptr, out, N);
}